// round 4
// baseline (speedup 1.0000x reference)
#include <cuda_runtime.h>

#define NN   50000
#define EE   800000
#define NG   500
#define C    100
#define OUTC 200
#define BN_EPS 1e-5f

// ---------------- scratch (device globals; no allocations) ----------------
__device__ int    d_fmt64;
__device__ int    d_src[EE];
__device__ int    d_dst[EE];
__device__ int    d_batch[NN];
__device__ int    d_indeg[NN];
__device__ int    d_row[NN + 1];
__device__ int    d_cursor[NN];
__device__ int    d_csrc[EE];
__device__ float  d_dinv[NN];
__device__ int    d_gstart[NG + 1];
__device__ __align__(16) float  d_m[NN * C];
__device__ __align__(16) float  d_agg[NN * C];
#define SGRID 98            // ceil(NN / 512)
__device__ float  d_psum[SGRID * C];
__device__ float  d_psq[SGRID * C];
__device__ __align__(16) float  d_scale[C];
__device__ __align__(16) float  d_shift[C];
__device__ __align__(16) float  d_pool[NG * C];

// ---------------- input decode (int64 vs int32 robust) ----------------
__global__ void k_detect(const long long* __restrict__ ei) {
    // If data is really int64 node indices, all values lie in [0, NN).
    // If it's int32 read as int64, high word = dst index -> huge values.
    int ok = 1;
    for (int i = 0; i < 64; i++) {
        long long v = ei[i];
        if (v < 0 || v >= NN) { ok = 0; break; }
    }
    d_fmt64 = ok;
}

__global__ void k_convert_edges(const void* __restrict__ eiv) {
    int e = blockIdx.x * blockDim.x + threadIdx.x;
    if (e >= EE) return;
    int s, d;
    if (d_fmt64) {
        const long long* p = (const long long*)eiv;
        s = (int)p[e]; d = (int)p[EE + e];
    } else {
        const int* p = (const int*)eiv;
        s = p[e]; d = p[EE + e];
    }
    if ((unsigned)s >= NN) s = 0;
    if ((unsigned)d >= NN) d = 0;
    d_src[e] = s;
    d_dst[e] = d;
}

__global__ void k_convert_batch(const void* __restrict__ bv) {
    int i = blockIdx.x * blockDim.x + threadIdx.x;
    if (i >= NN) return;
    int g;
    if (d_fmt64) g = (int)((const long long*)bv)[i];
    else         g = ((const int*)bv)[i];
    if ((unsigned)g >= NG) g = 0;
    d_batch[i] = g;
}

// ---------------- degree / CSR build ----------------
__global__ void k_indeg_zero() {
    int i = blockIdx.x * blockDim.x + threadIdx.x;
    if (i < NN) d_indeg[i] = 0;
}

__global__ void k_count() {
    int e = blockIdx.x * blockDim.x + threadIdx.x;
    if (e < EE) atomicAdd(&d_indeg[d_dst[e]], 1);
}

// single-block scan: row_ptr (exclusive prefix) + cursor copy
__global__ void k_scan() {
    __shared__ int part[1024];
    const int t = threadIdx.x;
    const int per = (NN + 1023) / 1024;
    const int base = t * per;
    int s = 0;
    for (int i = 0; i < per; i++) {
        int idx = base + i;
        if (idx < NN) s += d_indeg[idx];
    }
    part[t] = s;
    __syncthreads();
    for (int off = 1; off < 1024; off <<= 1) {
        int v = (t >= off) ? part[t - off] : 0;
        __syncthreads();
        part[t] += v;
        __syncthreads();
    }
    int run = (t > 0) ? part[t - 1] : 0;
    for (int i = 0; i < per; i++) {
        int idx = base + i;
        if (idx < NN) {
            d_row[idx] = run;
            d_cursor[idx] = run;
            run += d_indeg[idx];
        }
    }
    if (t == 0) d_row[NN] = EE;
}

__global__ void k_fill() {
    int e = blockIdx.x * blockDim.x + threadIdx.x;
    if (e < EE) {
        int p = atomicAdd(&d_cursor[d_dst[e]], 1);
        d_csrc[p] = d_src[e];
    }
}

__global__ void k_dinv() {
    int i = blockIdx.x * blockDim.x + threadIdx.x;
    if (i < NN) d_dinv[i] = rsqrtf((float)(d_indeg[i] + 1));   // +1 self-loop
}

// graph boundaries from sorted batch
__global__ void k_bounds() {
    int g = blockIdx.x * blockDim.x + threadIdx.x;
    if (g > NG) return;
    int lo = 0, hi = NN;
    while (lo < hi) {
        int mid = (lo + hi) >> 1;
        if (d_batch[mid] < g) lo = mid + 1; else hi = mid;
    }
    d_gstart[g] = lo;
}

// ---------------- GEMM: m = h @ W ; agg = dinv^2*m + b ----------------
// use_bn: read input from d_agg applying BN(scale,shift)+ReLU; else raw x (K=33)
#define MT 32
#define KC 50
__global__ void k_gemm(const float* __restrict__ in,
                       const float* __restrict__ W,
                       const float* __restrict__ bvec,
                       int K, int use_bn)
{
    __shared__ __align__(16) float Ws[KC][C];
    __shared__ float Hs[MT][KC + 2];

    const int tx  = threadIdx.x;          // 0..24  (4 cols each)
    const int ty  = threadIdx.y;          // 0..7   (4 rows each)
    const int tid = ty * 25 + tx;
    const int m0  = blockIdx.x * MT;

    float acc[4][4];
#pragma unroll
    for (int i = 0; i < 4; i++)
#pragma unroll
        for (int j = 0; j < 4; j++) acc[i][j] = 0.0f;

    for (int k0 = 0; k0 < K; k0 += KC) {
        const int kc = min(KC, K - k0);
        for (int idx = tid; idx < kc * C; idx += 200) {
            int kk = idx / C, cc = idx - kk * C;
            Ws[kk][cc] = W[(size_t)(k0 + kk) * C + cc];
        }
        for (int idx = tid; idx < MT * kc; idx += 200) {
            int rr = idx / kc, kk = idx - rr * kc;
            int r = m0 + rr;
            float v = 0.0f;
            if (r < NN) {
                int ch = k0 + kk;
                if (use_bn) {
                    v = d_agg[(size_t)r * C + ch];
                    v = fmaxf(v * d_scale[ch] + d_shift[ch], 0.0f);
                } else {
                    v = in[(size_t)r * K + ch];
                }
            }
            Hs[rr][kk] = v;
        }
        __syncthreads();

        for (int k = 0; k < kc; k++) {
            float4 w4 = *(const float4*)&Ws[k][tx * 4];
#pragma unroll
            for (int i = 0; i < 4; i++) {
                float a = Hs[ty * 4 + i][k];
                acc[i][0] = fmaf(a, w4.x, acc[i][0]);
                acc[i][1] = fmaf(a, w4.y, acc[i][1]);
                acc[i][2] = fmaf(a, w4.z, acc[i][2]);
                acc[i][3] = fmaf(a, w4.w, acc[i][3]);
            }
        }
        __syncthreads();
    }

    const int c0 = tx * 4;
    const float4 b4 = *(const float4*)&bvec[c0];
#pragma unroll
    for (int i = 0; i < 4; i++) {
        int r = m0 + ty * 4 + i;
        if (r < NN) {
            float dv = d_dinv[r];
            float d2 = dv * dv;
            float4 mv = make_float4(acc[i][0], acc[i][1], acc[i][2], acc[i][3]);
            *(float4*)&d_m[(size_t)r * C + c0] = mv;
            float4 av = make_float4(fmaf(d2, mv.x, b4.x), fmaf(d2, mv.y, b4.y),
                                    fmaf(d2, mv.z, b4.z), fmaf(d2, mv.w, b4.w));
            *(float4*)&d_agg[(size_t)r * C + c0] = av;
        }
    }
}

// ---------------- CSR gather: agg[dst] += sum_e dinv[src]*dinv[dst]*m[src] ----------------
__global__ void k_gather() {
    int warp = (blockIdx.x * blockDim.x + threadIdx.x) >> 5;
    int lane = threadIdx.x & 31;
    if (warp >= NN) return;
    const int beg = d_row[warp];
    const int end = d_row[warp + 1];
    const float dl = d_dinv[warp];
    float4 acc = make_float4(0.f, 0.f, 0.f, 0.f);
    if (lane < 25) acc = *(const float4*)&d_agg[(size_t)warp * C + lane * 4];
    for (int e = beg; e < end; e++) {
        int s = d_csrc[e];                 // warp-uniform -> broadcast
        float cf = dl * d_dinv[s];
        if (lane < 25) {
            const float4 mv = *(const float4*)&d_m[(size_t)s * C + lane * 4];
            acc.x = fmaf(cf, mv.x, acc.x);
            acc.y = fmaf(cf, mv.y, acc.y);
            acc.z = fmaf(cf, mv.z, acc.z);
            acc.w = fmaf(cf, mv.w, acc.w);
        }
    }
    if (lane < 25) *(float4*)&d_agg[(size_t)warp * C + lane * 4] = acc;
}

// ---------------- BN statistics (atomic-free, two stage) ----------------
#define ROWS_PER_BLOCK 512
__global__ void k_stats() {
    int c  = threadIdx.x;   // 0..99
    int ty = threadIdx.y;   // 0..3
    int r0 = blockIdx.x * ROWS_PER_BLOCK;
    int rend = min(r0 + ROWS_PER_BLOCK, NN);
    float s = 0.0f, q = 0.0f;
    for (int r = r0 + ty; r < rend; r += 4) {
        float v = d_agg[(size_t)r * C + c];
        s += v;
        q = fmaf(v, v, q);
    }
    __shared__ float sh_s[4][C], sh_q[4][C];
    sh_s[ty][c] = s;
    sh_q[ty][c] = q;
    __syncthreads();
    if (ty == 0) {
        d_psum[blockIdx.x * C + c] = sh_s[0][c] + sh_s[1][c] + sh_s[2][c] + sh_s[3][c];
        d_psq [blockIdx.x * C + c] = sh_q[0][c] + sh_q[1][c] + sh_q[2][c] + sh_q[3][c];
    }
}

__global__ void k_finalize(const float* __restrict__ gamma,
                           const float* __restrict__ beta) {
    int c = threadIdx.x;
    if (c >= C) return;
    float S = 0.0f, Q = 0.0f;
    for (int bkt = 0; bkt < SGRID; bkt++) {
        S += d_psum[bkt * C + c];
        Q += d_psq [bkt * C + c];
    }
    float mean = S * (1.0f / (float)NN);
    float var  = Q * (1.0f / (float)NN) - mean * mean;
    float rstd = rsqrtf(var + BN_EPS);
    float sc = rstd * gamma[c];
    d_scale[c] = sc;
    d_shift[c] = beta[c] - mean * sc;
}

// ---------------- pooling: per-graph segment sum (batch is sorted) ----------------
__global__ void k_pool() {
    int g = blockIdx.x;
    int c = threadIdx.x;
    if (c >= C) return;
    int r0 = d_gstart[g], r1 = d_gstart[g + 1];
    float s = 0.0f;
    for (int r = r0; r < r1; r++) s += d_agg[(size_t)r * C + c];
    d_pool[g * C + c] = fmaf(d_scale[c], s, (float)(r1 - r0) * d_shift[c]);
}

// ---------------- output head: out = leaky_relu(pool @ Wout + bout) ----------------
__global__ void k_out(const float* __restrict__ Wout,
                      const float* __restrict__ bout,
                      float* __restrict__ out) {
    int t = blockIdx.x * blockDim.x + threadIdx.x;
    if (t >= NG * OUTC) return;
    int g = t / OUTC;
    int c = t - g * OUTC;
    float acc = bout[c];
#pragma unroll 4
    for (int k = 0; k < C; k++)
        acc = fmaf(d_pool[g * C + k], Wout[(size_t)k * OUTC + c], acc);
    out[t] = acc > 0.0f ? acc : 0.1f * acc;
}

// ---------------- launch ----------------
extern "C" void kernel_launch(void* const* d_in, const int* in_sizes, int n_in,
                              void* d_out, int out_size) {
    // Identify inputs by element count (robust to metadata ordering).
    const float *x = 0, *W0 = 0, *Wrest = 0, *bb = 0, *gamma = 0, *beta = 0,
                *Wout = 0, *bout = 0;
    const void *ei = 0, *batch = 0;
    for (int i = 0; i < n_in; i++) {
        switch (in_sizes[i]) {
            case 1650000: x     = (const float*)d_in[i]; break;  // 50000 x 33
            case 1600000: ei    = d_in[i];               break;  // 2 x 800000
            case 50000:   batch = d_in[i];               break;
            case 3300:    W0    = (const float*)d_in[i]; break;  // 33 x 100
            case 30000:   Wrest = (const float*)d_in[i]; break;  // 3 x 100 x 100
            case 20000:   Wout  = (const float*)d_in[i]; break;  // 100 x 200
            case 200:     bout  = (const float*)d_in[i]; break;
            case 400:                                            // b, gamma, beta in order
                if (!bb) bb = (const float*)d_in[i];
                else if (!gamma) gamma = (const float*)d_in[i];
                else beta = (const float*)d_in[i];
                break;
            default: break;
        }
    }
    if (!x)     x     = (const float*)d_in[0];
    if (!ei)    ei    = d_in[1];
    if (!batch) batch = d_in[2];
    if (!W0)    W0    = (const float*)d_in[3];
    if (!Wrest) Wrest = (const float*)d_in[4];
    if (!bb)    bb    = (const float*)d_in[5];
    if (!gamma) gamma = (const float*)d_in[6];
    if (!beta)  beta  = (const float*)d_in[7];
    if (!Wout)  Wout  = (const float*)d_in[8];
    if (!bout)  bout  = (const float*)d_in[9];
    float* out = (float*)d_out;

    k_detect<<<1, 1>>>((const long long*)ei);
    k_convert_edges<<<(EE + 255) / 256, 256>>>(ei);
    k_convert_batch<<<(NN + 255) / 256, 256>>>(batch);

    k_indeg_zero<<<(NN + 255) / 256, 256>>>();
    k_count<<<(EE + 255) / 256, 256>>>();
    k_scan<<<1, 1024>>>();
    k_fill<<<(EE + 255) / 256, 256>>>();
    k_dinv<<<(NN + 255) / 256, 256>>>();
    k_bounds<<<2, 512>>>();

    const int gemm_grid = (NN + MT - 1) / MT;
    const dim3 gemm_blk(25, 8);
    const int gather_grid = (NN * 32 + 255) / 256;
    const dim3 stats_blk(C, 4);

    for (int L = 0; L < 4; L++) {
        const float* W = (L == 0) ? W0 : (Wrest + (size_t)(L - 1) * C * C);
        const int K = (L == 0) ? 33 : C;
        const float* in = (L == 0) ? x : (const float*)0;

        k_gemm<<<gemm_grid, gemm_blk>>>(in, W, bb + L * C, K, L > 0 ? 1 : 0);
        k_gather<<<gather_grid, 256>>>();
        k_stats<<<SGRID, stats_blk>>>();
        k_finalize<<<1, 128>>>(gamma + L * C, beta + L * C);
    }

    k_pool<<<NG, 128>>>();
    k_out<<<(NG * OUTC + 255) / 256, 256>>>(Wout, bout, out);
}